// round 13
// baseline (speedup 1.0000x reference)
#include <cuda_runtime.h>
#include <cuda_bf16.h>
#include <math.h>
#include <stdint.h>

#define Bsz   8
#define Lseq  8192
#define Hdim  1024
#define NS    64
#define NTAP  48
#define M_TOT (Bsz * Lseq)   // 65536

typedef unsigned short ushort_t;

// ---------------- scratch ----------------
__device__ float    g_u[(size_t)M_TOT * NS];        // 16 MB
__device__ ushort_t g_ch[(size_t)M_TOT * NS];       // 8 MB  conv hi (bf16 bits)
__device__ ushort_t g_cl[(size_t)M_TOT * NS];       // 8 MB  conv lo
__device__ ushort_t g_pinH[NS * Hdim], g_pinL[NS * Hdim];       // [n][k]
__device__ ushort_t g_poutH[Hdim * NS], g_poutL[Hdim * NS];     // [n][k]
__device__ float g_kre[NTAP * NS];
__device__ float g_kim[NTAP * NS];

__device__ __forceinline__ uint32_t pack2(__nv_bfloat16 a, __nv_bfloat16 b) {
    return (uint32_t)__bfloat16_as_ushort(a) | ((uint32_t)__bfloat16_as_ushort(b) << 16);
}
__device__ __forceinline__ void split2(float x, __nv_bfloat16& h, __nv_bfloat16& l) {
    h = __float2bfloat16(x);
    l = __float2bfloat16(x - __bfloat162float(h));
}
__device__ __forceinline__ void mma16816(float* c, const uint32_t* a, const uint32_t* b) {
    asm volatile(
        "mma.sync.aligned.m16n8k16.row.col.f32.bf16.bf16.f32 "
        "{%0,%1,%2,%3}, {%4,%5,%6,%7}, {%8,%9}, {%0,%1,%2,%3};"
        : "+f"(c[0]), "+f"(c[1]), "+f"(c[2]), "+f"(c[3])
        : "r"(a[0]), "r"(a[1]), "r"(a[2]), "r"(a[3]), "r"(b[0]), "r"(b[1]));
}
__device__ __forceinline__ uint32_t cvta_smem(const void* p) {
    uint32_t a;
    asm("{ .reg .u64 t; cvta.to.shared.u64 t, %1; cvt.u32.u64 %0, t; }" : "=r"(a) : "l"(p));
    return a;
}
__device__ __forceinline__ void ldsm_x4(uint32_t* r, uint32_t addr) {
    asm volatile("ldmatrix.sync.aligned.m8n8.x4.shared.b16 {%0,%1,%2,%3}, [%4];"
                 : "=r"(r[0]), "=r"(r[1]), "=r"(r[2]), "=r"(r[3]) : "r"(addr));
}

// ---------------- taps ----------------
__global__ void taps_kernel(const float* __restrict__ freq, const float* __restrict__ dec) {
    int d = blockIdx.x;
    int n = threadIdx.x;
    double rho = -exp((double)dec[n]);
    double th  = (double)freq[n];
    double mag = exp(rho * (double)d);
    double ph  = th * (double)d;
    g_kre[d * NS + n] = (float)(mag * cos(ph));
    g_kim[d * NS + n] = (float)(mag * sin(ph));
}

// ---------------- projection planes: bf16 hi/lo, [n][k] ----------------
__global__ void __launch_bounds__(256) prep_planes(const float* __restrict__ pin,
                                                   const float* __restrict__ pout) {
    int idx = blockIdx.x * 256 + threadIdx.x;   // 0..131071
    __nv_bfloat16 h, l;
    if (idx < NS * Hdim) {                      // pin: [n<64][k<1024]
        int n = idx >> 10, k = idx & 1023;
        split2(pin[(size_t)k * NS + n], h, l);
        g_pinH[idx] = __bfloat16_as_ushort(h);
        g_pinL[idx] = __bfloat16_as_ushort(l);
    } else {                                    // pout: [n<1024][k<64]
        int j = idx - NS * Hdim;
        int n = j >> 6, k = j & 63;
        split2(pout[(size_t)k * Hdim + n], h, l);
        g_poutH[j] = __bfloat16_as_ushort(h);
        g_poutL[j] = __bfloat16_as_ushort(l);
    }
}

#define RS 80   // gemmA: 64B data + 16B pad

// ============ GEMM A (HMMA, reg-prefetch pipeline): g_u = input @ P_in ============
__global__ void __launch_bounds__(256) gemmA_mma(const float* __restrict__ A) {
    __shared__ char sm[30720];
    char* Ah = sm;
    char* Al = sm + 10240;
    char* Bh = sm + 20480;
    char* Bl = sm + 25600;

    int tid = threadIdx.x;
    int m0  = blockIdx.x * 128;
    int w   = tid >> 5, l = tid & 31;
    int wm  = w >> 1, wn = w & 1;          // warp tile 32m x 32n
    int lr  = l >> 2, lc = l & 3;
    int lrow = l & 15, lhalf = (l >> 4) * 16;

    int ra[4], qa[4];
#pragma unroll
    for (int t = 0; t < 4; ++t) { int idx = t * 256 + tid; ra[t] = idx >> 3; qa[t] = idx & 7; }
    int rB = tid >> 2, qB = tid & 3;

    uint32_t smb = cvta_smem(sm);

    float acc[2][4][4];
#pragma unroll
    for (int i = 0; i < 2; i++)
#pragma unroll
        for (int j = 0; j < 4; j++)
#pragma unroll
            for (int q = 0; q < 4; q++) acc[i][j][q] = 0.f;

    // prologue: prefetch chunk 0
    float4 areg[4];
    uint4 bhreg, blreg;
#pragma unroll
    for (int t = 0; t < 4; ++t)
        areg[t] = *(const float4*)&A[(size_t)(m0 + ra[t]) * Hdim + qa[t] * 4];
    bhreg = *(const uint4*)&g_pinH[rB * Hdim + qB * 8];
    blreg = *(const uint4*)&g_pinL[rB * Hdim + qB * 8];

    for (int c = 0; c < 32; ++c) {
        // STS current chunk
#pragma unroll
        for (int t = 0; t < 4; ++t) {
            __nv_bfloat16 h0, h1, h2, h3, l0, l1, l2, l3;
            split2(areg[t].x, h0, l0); split2(areg[t].y, h1, l1);
            split2(areg[t].z, h2, l2); split2(areg[t].w, h3, l3);
            *(uint2*)(Ah + ra[t] * RS + qa[t] * 8) = make_uint2(pack2(h0, h1), pack2(h2, h3));
            *(uint2*)(Al + ra[t] * RS + qa[t] * 8) = make_uint2(pack2(l0, l1), pack2(l2, l3));
        }
        *(uint4*)(Bh + rB * RS + qB * 16) = bhreg;
        *(uint4*)(Bl + rB * RS + qB * 16) = blreg;
        __syncthreads();

        // prefetch next chunk (overlaps with MMA below)
        if (c < 31) {
            int k1 = (c + 1) * 32;
#pragma unroll
            for (int t = 0; t < 4; ++t)
                areg[t] = *(const float4*)&A[(size_t)(m0 + ra[t]) * Hdim + k1 + qa[t] * 4];
            bhreg = *(const uint4*)&g_pinH[rB * Hdim + k1 + qB * 8];
            blreg = *(const uint4*)&g_pinL[rB * Hdim + k1 + qB * 8];
        }

#pragma unroll
        for (int ks = 0; ks < 2; ++ks) {
            int kb = ks * 32;
            uint32_t ah[2][4], al[2][4];
#pragma unroll
            for (int mt = 0; mt < 2; ++mt) {
                uint32_t off = (uint32_t)((wm * 32 + mt * 16 + lrow) * RS + kb + lhalf);
                ldsm_x4(ah[mt], smb + off);
                ldsm_x4(al[mt], smb + 10240 + off);
            }
#pragma unroll
            for (int nt = 0; nt < 4; ++nt) {
                int n0 = wn * 32 + nt * 8 + lr;
                int co = kb + lc * 4;
                uint32_t bh[2], bl[2];
                bh[0] = *(const uint32_t*)(Bh + n0 * RS + co);
                bh[1] = *(const uint32_t*)(Bh + n0 * RS + co + 16);
                bl[0] = *(const uint32_t*)(Bl + n0 * RS + co);
                bl[1] = *(const uint32_t*)(Bl + n0 * RS + co + 16);
#pragma unroll
                for (int mt = 0; mt < 2; ++mt) {
                    mma16816(acc[mt][nt], ah[mt], bh);
                    mma16816(acc[mt][nt], ah[mt], bl);
                    mma16816(acc[mt][nt], al[mt], bh);
                }
            }
        }
        __syncthreads();
    }
#pragma unroll
    for (int mt = 0; mt < 2; ++mt) {
        size_t mrow = (size_t)m0 + wm * 32 + mt * 16 + lr;
#pragma unroll
        for (int nt = 0; nt < 4; ++nt) {
            int n = wn * 32 + nt * 8 + lc * 2;
            *(float2*)&g_u[mrow * NS + n]       = make_float2(acc[mt][nt][0], acc[mt][nt][1]);
            *(float2*)&g_u[(mrow + 8) * NS + n] = make_float2(acc[mt][nt][2], acc[mt][nt][3]);
        }
    }
}

// ---------------- FIR (NTAP=48, TL=64) -> bf16 hi/lo planes; folded final-state ----------------
#define TL  64
#define WIN (TL + NTAP)   // 112 rows
__global__ void __launch_bounds__(256) fir_kernel(const float* __restrict__ init_state,
                                                  float* __restrict__ outp, int mode) {
    __shared__ float us[WIN * NS];
    int b    = blockIdx.x >> 7;
    int lblk = blockIdx.x & 127;
    int l0   = lblk * TL;
    int base_i = (l0 + 1) - (NTAP - 1);
    int tid  = threadIdx.x;

    for (int idx = tid; idx < WIN * NS; idx += 256) {
        int row = idx >> 6;
        int n   = idx & 63;
        int i   = base_i + row;
        float v;
        if (i < 0)        v = 0.f;
        else if (i == 0)  v = init_state[b * NS + n];
        else              v = g_u[((size_t)b * Lseq + (i - 1)) * NS + n];
        us[idx] = v;
    }
    __syncthreads();

    int n  = tid & 63;
    int lt = tid >> 6;
#pragma unroll
    for (int g = 0; g < 2; ++g) {
        int lb  = lt * 16 + g * 8;
        int off = lb + NTAP - 1;
        float acc[8];
#pragma unroll
        for (int r = 0; r < 8; r++) acc[r] = 0.f;
#pragma unroll
        for (int dc = 0; dc < NTAP; dc += 8) {
            float kk[8];
#pragma unroll
            for (int t = 0; t < 8; t++) kk[t] = g_kre[(dc + t) * NS + n];
            float uu[15];
#pragma unroll
            for (int t = 0; t < 15; t++) uu[t] = us[(off - dc - 7 + t) * NS + n];
#pragma unroll
            for (int d = 0; d < 8; ++d)
#pragma unroll
                for (int r = 0; r < 8; r++) acc[r] += kk[d] * uu[7 + r - d];
        }
#pragma unroll
        for (int r = 0; r < 8; r++) {
            size_t o = ((size_t)b * Lseq + l0 + lb + r) * NS + n;
            __nv_bfloat16 h, lo;
            split2(acc[r], h, lo);
            g_ch[o] = __bfloat16_as_ushort(h);
            g_cl[o] = __bfloat16_as_ushort(lo);
        }
    }

    // folded final state s_L (complex) -> tail of d_out
    if (lblk == 127 && mode != 0 && tid < 64) {
        float re = 0.f, im = 0.f;
#pragma unroll 4
        for (int d = 0; d < NTAP; ++d) {
            float u = us[(Lseq - d - base_i) * NS + tid];
            re += g_kre[d * NS + tid] * u;
            im += g_kim[d * NS + tid] * u;
        }
        float* base = outp + (size_t)M_TOT * Hdim;
        if (mode == 2) {
            base[((size_t)b * NS + tid) * 2 + 0] = re;
            base[((size_t)b * NS + tid) * 2 + 1] = im;
        } else {
            base[(size_t)b * NS + tid] = re;
        }
    }
}

// ============ GEMM B (HMMA, single K-pass, NLOOP n-chunks per CTA) ============
// out[M,1024] = conv[M,64] @ P_out[64,1024]
// 72 KB dynamic smem: Ah Al (staged once) Bh Bl (re-staged per n-chunk); RS2=144
#define RS2 144
#define NLOOP 2
#define GB_SMEM (4 * 128 * RS2)   // 73728
__global__ void __launch_bounds__(256, 2) gemmB_mma(float* __restrict__ C) {
    extern __shared__ char dsm[];
    int tid = threadIdx.x;
    int nbase = blockIdx.x * (128 * NLOOP);
    int m0  = blockIdx.y * 128;
    int w   = tid >> 5, l = tid & 31;
    int wm  = w >> 1, wn = w & 1;          // warp tile 32m x 64n
    int lr  = l >> 2, lc = l & 3;
    int lrow = l & 15, lhalf = (l >> 4) * 16;

    char* Ah = dsm;
    char* Al = dsm + 18432;
    char* Bh = dsm + 36864;
    char* Bl = dsm + 55296;
    uint32_t smb = cvta_smem(dsm);

    // stage A planes ONCE (reused across NLOOP n-chunks)
#pragma unroll
    for (int t = 0; t < 4; ++t) {
        int idx = t * 256 + tid;
        int r = idx >> 3, q = idx & 7;
        *(uint4*)(Ah + r * RS2 + q * 16) = *(const uint4*)&g_ch[(size_t)(m0 + r) * NS + q * 8];
        *(uint4*)(Al + r * RS2 + q * 16) = *(const uint4*)&g_cl[(size_t)(m0 + r) * NS + q * 8];
    }
    // stage B chunk 0
#pragma unroll
    for (int t = 0; t < 4; ++t) {
        int idx = t * 256 + tid;
        int r = idx >> 3, q = idx & 7;
        *(uint4*)(Bh + r * RS2 + q * 16) = *(const uint4*)&g_poutH[(size_t)(nbase + r) * NS + q * 8];
        *(uint4*)(Bl + r * RS2 + q * 16) = *(const uint4*)&g_poutL[(size_t)(nbase + r) * NS + q * 8];
    }
    __syncthreads();

    for (int nc = 0; nc < NLOOP; ++nc) {
        int n0c = nbase + nc * 128;

        float acc[2][8][4];
#pragma unroll
        for (int i = 0; i < 2; i++)
#pragma unroll
            for (int j = 0; j < 8; j++)
#pragma unroll
                for (int q = 0; q < 4; q++) acc[i][j][q] = 0.f;

#pragma unroll
        for (int kstep = 0; kstep < 4; ++kstep) {
            int kb = kstep * 32;   // byte offset of 16-element k group
            uint32_t ah[2][4], al[2][4];
#pragma unroll
            for (int mt = 0; mt < 2; ++mt) {
                uint32_t off = (uint32_t)((wm * 32 + mt * 16 + lrow) * RS2 + kb + lhalf);
                ldsm_x4(ah[mt], smb + off);
                ldsm_x4(al[mt], smb + 18432 + off);
            }
#pragma unroll
            for (int nt = 0; nt < 8; ++nt) {
                int n0 = wn * 64 + nt * 8 + lr;
                int co = kb + lc * 4;
                uint32_t bh[2], bl[2];
                bh[0] = *(const uint32_t*)(Bh + n0 * RS2 + co);
                bh[1] = *(const uint32_t*)(Bh + n0 * RS2 + co + 16);
                bl[0] = *(const uint32_t*)(Bl + n0 * RS2 + co);
                bl[1] = *(const uint32_t*)(Bl + n0 * RS2 + co + 16);
#pragma unroll
                for (int mt = 0; mt < 2; ++mt) {
                    mma16816(acc[mt][nt], ah[mt], bh);
                    mma16816(acc[mt][nt], ah[mt], bl);
                    mma16816(acc[mt][nt], al[mt], bh);
                }
            }
        }
        // epilogue for this n-chunk
#pragma unroll
        for (int mt = 0; mt < 2; ++mt) {
            size_t mrow = (size_t)m0 + wm * 32 + mt * 16 + lr;
#pragma unroll
            for (int nt = 0; nt < 8; ++nt) {
                int n = n0c + wn * 64 + nt * 8 + lc * 2;
                *(float2*)&C[mrow * Hdim + n]       = make_float2(acc[mt][nt][0], acc[mt][nt][1]);
                *(float2*)&C[(mrow + 8) * Hdim + n] = make_float2(acc[mt][nt][2], acc[mt][nt][3]);
            }
        }
        // restage B for next chunk
        if (nc + 1 < NLOOP) {
            __syncthreads();   // all warps done reading current B
            int n1 = n0c + 128;
#pragma unroll
            for (int t = 0; t < 4; ++t) {
                int idx = t * 256 + tid;
                int r = idx >> 3, q = idx & 7;
                *(uint4*)(Bh + r * RS2 + q * 16) = *(const uint4*)&g_poutH[(size_t)(n1 + r) * NS + q * 8];
                *(uint4*)(Bl + r * RS2 + q * 16) = *(const uint4*)&g_poutL[(size_t)(n1 + r) * NS + q * 8];
            }
            __syncthreads();
        }
    }
}

// ---------------- launch ----------------
extern "C" void kernel_launch(void* const* d_in, const int* in_sizes, int n_in,
                              void* d_out, int out_size) {
    const float* input = (const float*)d_in[0];
    const float* init  = (const float*)d_in[1];
    const float* pin   = (const float*)d_in[2];
    const float* pout  = (const float*)d_in[3];
    const float* freq  = (const float*)d_in[4];
    const float* dec   = (const float*)d_in[5];
    float* out = (float*)d_out;

    cudaFuncSetAttribute(gemmB_mma, cudaFuncAttributeMaxDynamicSharedMemorySize, GB_SMEM);

    long long tail = (long long)out_size - (long long)M_TOT * Hdim;
    int mode = 0;
    if (tail >= (long long)Bsz * NS * 2)  mode = 2;
    else if (tail >= (long long)Bsz * NS) mode = 1;

    taps_kernel<<<NTAP, NS>>>(freq, dec);
    prep_planes<<<512, 256>>>(pin, pout);
    gemmA_mma<<<M_TOT / 128, 256>>>(input);
    fir_kernel<<<Bsz * (Lseq / TL), 256>>>(init, out, mode);
    gemmB_mma<<<dim3(Hdim / (128 * NLOOP), M_TOT / 128), 256, GB_SMEM>>>(out);
}

// round 14
// speedup vs baseline: 1.1464x; 1.1464x over previous
#include <cuda_runtime.h>
#include <cuda_fp16.h>
#include <math.h>
#include <stdint.h>

#define Bsz   8
#define Lseq  8192
#define Hdim  1024
#define NS    64
#define NTAP  48
#define M_TOT (Bsz * Lseq)   // 65536

typedef unsigned short ushort_t;

// ---------------- scratch ----------------
__device__ float    g_u[(size_t)M_TOT * NS];        // 16 MB
__device__ ushort_t g_ch[(size_t)M_TOT * NS];       // 8 MB  conv hi (fp16 bits)
__device__ ushort_t g_cl[(size_t)M_TOT * NS];       // 8 MB  conv lo (fp16 bits)
__device__ ushort_t g_pinF[NS * Hdim];              // [n][k] single fp16
__device__ ushort_t g_poutF[Hdim * NS];             // [n][k] single fp16
__device__ float g_kre[NTAP * NS];
__device__ float g_kim[NTAP * NS];

__device__ __forceinline__ uint32_t pack2h(__half a, __half b) {
    return (uint32_t)__half_as_ushort(a) | ((uint32_t)__half_as_ushort(b) << 16);
}
__device__ __forceinline__ void split2h(float x, __half& h, __half& l) {
    h = __float2half(x);
    l = __float2half(x - __half2float(h));
}
// f32.f16.f16.f32 HMMA (sm_80+, legal under compute_103)
__device__ __forceinline__ void mma16816h(float* c, const uint32_t* a, const uint32_t* b) {
    asm volatile(
        "mma.sync.aligned.m16n8k16.row.col.f32.f16.f16.f32 "
        "{%0,%1,%2,%3}, {%4,%5,%6,%7}, {%8,%9}, {%0,%1,%2,%3};"
        : "+f"(c[0]), "+f"(c[1]), "+f"(c[2]), "+f"(c[3])
        : "r"(a[0]), "r"(a[1]), "r"(a[2]), "r"(a[3]), "r"(b[0]), "r"(b[1]));
}
__device__ __forceinline__ uint32_t cvta_smem(const void* p) {
    uint32_t a;
    asm("{ .reg .u64 t; cvta.to.shared.u64 t, %1; cvt.u32.u64 %0, t; }" : "=r"(a) : "l"(p));
    return a;
}
__device__ __forceinline__ void ldsm_x4(uint32_t* r, uint32_t addr) {
    asm volatile("ldmatrix.sync.aligned.m8n8.x4.shared.b16 {%0,%1,%2,%3}, [%4];"
                 : "=r"(r[0]), "=r"(r[1]), "=r"(r[2]), "=r"(r[3]) : "r"(addr));
}

// ---------------- taps ----------------
__global__ void taps_kernel(const float* __restrict__ freq, const float* __restrict__ dec) {
    int d = blockIdx.x;
    int n = threadIdx.x;
    double rho = -exp((double)dec[n]);
    double th  = (double)freq[n];
    double mag = exp(rho * (double)d);
    double ph  = th * (double)d;
    g_kre[d * NS + n] = (float)(mag * cos(ph));
    g_kim[d * NS + n] = (float)(mag * sin(ph));
}

// ---------------- projection planes: single fp16, [n][k] ----------------
__global__ void __launch_bounds__(256) prep_planes(const float* __restrict__ pin,
                                                   const float* __restrict__ pout) {
    int idx = blockIdx.x * 256 + threadIdx.x;   // 0..131071
    if (idx < NS * Hdim) {                      // pin: [n<64][k<1024]
        int n = idx >> 10, k = idx & 1023;
        g_pinF[idx] = __half_as_ushort(__float2half(pin[(size_t)k * NS + n]));
    } else {                                    // pout: [n<1024][k<64]
        int j = idx - NS * Hdim;
        int n = j >> 6, k = j & 63;
        g_poutF[j] = __half_as_ushort(__float2half(pout[(size_t)k * Hdim + n]));
    }
}

#define RS 80   // gemmA: 64B data + 16B pad

// ============ GEMM A (HMMA fp16 2-term): g_u[M,64] = input[M,1024] @ P_in[1024,64] ============
// smem: Ah(10240) Al(10240) Bf(5120) = 25600 static
__global__ void __launch_bounds__(256) gemmA_mma(const float* __restrict__ A) {
    __shared__ char sm[25600];
    char* Ah = sm;
    char* Al = sm + 10240;
    char* Bf = sm + 20480;

    int tid = threadIdx.x;
    int m0  = blockIdx.x * 128;
    int w   = tid >> 5, l = tid & 31;
    int wm  = w >> 1, wn = w & 1;          // warp tile 32m x 32n
    int lr  = l >> 2, lc = l & 3;
    int lrow = l & 15, lhalf = (l >> 4) * 16;

    int ra[4], qa[4];
#pragma unroll
    for (int t = 0; t < 4; ++t) { int idx = t * 256 + tid; ra[t] = idx >> 3; qa[t] = idx & 7; }
    int rB = tid >> 2, qB = tid & 3;

    uint32_t smb = cvta_smem(sm);

    float acc[2][4][4];
#pragma unroll
    for (int i = 0; i < 2; i++)
#pragma unroll
        for (int j = 0; j < 4; j++)
#pragma unroll
            for (int q = 0; q < 4; q++) acc[i][j][q] = 0.f;

    // prologue: prefetch chunk 0
    float4 areg[4];
    uint4 bfreg;
#pragma unroll
    for (int t = 0; t < 4; ++t)
        areg[t] = *(const float4*)&A[(size_t)(m0 + ra[t]) * Hdim + qa[t] * 4];
    bfreg = *(const uint4*)&g_pinF[rB * Hdim + qB * 8];

    for (int c = 0; c < 32; ++c) {
        // STS current chunk
#pragma unroll
        for (int t = 0; t < 4; ++t) {
            __half h0, h1, h2, h3, l0, l1, l2, l3;
            split2h(areg[t].x, h0, l0); split2h(areg[t].y, h1, l1);
            split2h(areg[t].z, h2, l2); split2h(areg[t].w, h3, l3);
            *(uint2*)(Ah + ra[t] * RS + qa[t] * 8) = make_uint2(pack2h(h0, h1), pack2h(h2, h3));
            *(uint2*)(Al + ra[t] * RS + qa[t] * 8) = make_uint2(pack2h(l0, l1), pack2h(l2, l3));
        }
        *(uint4*)(Bf + rB * RS + qB * 16) = bfreg;
        __syncthreads();

        // prefetch next chunk (overlaps with MMA below)
        if (c < 31) {
            int k1 = (c + 1) * 32;
#pragma unroll
            for (int t = 0; t < 4; ++t)
                areg[t] = *(const float4*)&A[(size_t)(m0 + ra[t]) * Hdim + k1 + qa[t] * 4];
            bfreg = *(const uint4*)&g_pinF[rB * Hdim + k1 + qB * 8];
        }

#pragma unroll
        for (int ks = 0; ks < 2; ++ks) {
            int kb = ks * 32;
            uint32_t ah[2][4], al[2][4];
#pragma unroll
            for (int mt = 0; mt < 2; ++mt) {
                uint32_t off = (uint32_t)((wm * 32 + mt * 16 + lrow) * RS + kb + lhalf);
                ldsm_x4(ah[mt], smb + off);
                ldsm_x4(al[mt], smb + 10240 + off);
            }
#pragma unroll
            for (int nt = 0; nt < 4; ++nt) {
                int n0 = wn * 32 + nt * 8 + lr;
                int co = kb + lc * 4;
                uint32_t bf[2];
                bf[0] = *(const uint32_t*)(Bf + n0 * RS + co);
                bf[1] = *(const uint32_t*)(Bf + n0 * RS + co + 16);
#pragma unroll
                for (int mt = 0; mt < 2; ++mt) {
                    mma16816h(acc[mt][nt], ah[mt], bf);
                    mma16816h(acc[mt][nt], al[mt], bf);
                }
            }
        }
        __syncthreads();
    }
#pragma unroll
    for (int mt = 0; mt < 2; ++mt) {
        size_t mrow = (size_t)m0 + wm * 32 + mt * 16 + lr;
#pragma unroll
        for (int nt = 0; nt < 4; ++nt) {
            int n = wn * 32 + nt * 8 + lc * 2;
            *(float2*)&g_u[mrow * NS + n]       = make_float2(acc[mt][nt][0], acc[mt][nt][1]);
            *(float2*)&g_u[(mrow + 8) * NS + n] = make_float2(acc[mt][nt][2], acc[mt][nt][3]);
        }
    }
}

// ---------------- FIR (NTAP=48, TL=64) -> fp16 hi/lo planes; folded final-state ----------------
#define TL  64
#define WIN (TL + NTAP)   // 112 rows
__global__ void __launch_bounds__(256) fir_kernel(const float* __restrict__ init_state,
                                                  float* __restrict__ outp, int mode) {
    __shared__ float us[WIN * NS];
    int b    = blockIdx.x >> 7;
    int lblk = blockIdx.x & 127;
    int l0   = lblk * TL;
    int base_i = (l0 + 1) - (NTAP - 1);
    int tid  = threadIdx.x;

    for (int idx = tid; idx < WIN * NS; idx += 256) {
        int row = idx >> 6;
        int n   = idx & 63;
        int i   = base_i + row;
        float v;
        if (i < 0)        v = 0.f;
        else if (i == 0)  v = init_state[b * NS + n];
        else              v = g_u[((size_t)b * Lseq + (i - 1)) * NS + n];
        us[idx] = v;
    }
    __syncthreads();

    int n  = tid & 63;
    int lt = tid >> 6;
#pragma unroll
    for (int g = 0; g < 2; ++g) {
        int lb  = lt * 16 + g * 8;
        int off = lb + NTAP - 1;
        float acc[8];
#pragma unroll
        for (int r = 0; r < 8; r++) acc[r] = 0.f;
#pragma unroll
        for (int dc = 0; dc < NTAP; dc += 8) {
            float kk[8];
#pragma unroll
            for (int t = 0; t < 8; t++) kk[t] = g_kre[(dc + t) * NS + n];
            float uu[15];
#pragma unroll
            for (int t = 0; t < 15; t++) uu[t] = us[(off - dc - 7 + t) * NS + n];
#pragma unroll
            for (int d = 0; d < 8; ++d)
#pragma unroll
                for (int r = 0; r < 8; r++) acc[r] += kk[d] * uu[7 + r - d];
        }
#pragma unroll
        for (int r = 0; r < 8; r++) {
            size_t o = ((size_t)b * Lseq + l0 + lb + r) * NS + n;
            __half h, lo;
            split2h(acc[r], h, lo);
            g_ch[o] = __half_as_ushort(h);
            g_cl[o] = __half_as_ushort(lo);
        }
    }

    // folded final state s_L (complex) -> tail of d_out (full fp32 path)
    if (lblk == 127 && mode != 0 && tid < 64) {
        float re = 0.f, im = 0.f;
#pragma unroll 4
        for (int d = 0; d < NTAP; ++d) {
            float u = us[(Lseq - d - base_i) * NS + tid];
            re += g_kre[d * NS + tid] * u;
            im += g_kim[d * NS + tid] * u;
        }
        float* base = outp + (size_t)M_TOT * Hdim;
        if (mode == 2) {
            base[((size_t)b * NS + tid) * 2 + 0] = re;
            base[((size_t)b * NS + tid) * 2 + 1] = im;
        } else {
            base[(size_t)b * NS + tid] = re;
        }
    }
}

// ============ GEMM B (HMMA fp16 2-term, single K-pass): out = conv @ P_out ============
// smem: Ah(18432) Al(18432) Bf(18432) = 55296; RS2=144
#define RS2 144
#define GB_SMEM (3 * 128 * RS2)   // 55296
__global__ void __launch_bounds__(256, 2) gemmB_mma(float* __restrict__ C) {
    extern __shared__ char dsm[];
    int tid = threadIdx.x;
    int n0c = blockIdx.x * 128;
    int m0  = blockIdx.y * 128;
    int w   = tid >> 5, l = tid & 31;
    int wm  = w >> 1, wn = w & 1;          // warp tile 32m x 64n
    int lr  = l >> 2, lc = l & 3;
    int lrow = l & 15, lhalf = (l >> 4) * 16;

    char* Ah = dsm;
    char* Al = dsm + 18432;
    char* Bf = dsm + 36864;
    uint32_t smb = cvta_smem(dsm);

    float acc[2][8][4];
#pragma unroll
    for (int i = 0; i < 2; i++)
#pragma unroll
        for (int j = 0; j < 8; j++)
#pragma unroll
            for (int q = 0; q < 4; q++) acc[i][j][q] = 0.f;

    // staging: full K=64; pure uint4 copies (3 planes)
#pragma unroll
    for (int t = 0; t < 4; ++t) {
        int idx = t * 256 + tid;
        int r = idx >> 3, q = idx & 7;
        *(uint4*)(Ah + r * RS2 + q * 16) = *(const uint4*)&g_ch[(size_t)(m0 + r) * NS + q * 8];
        *(uint4*)(Al + r * RS2 + q * 16) = *(const uint4*)&g_cl[(size_t)(m0 + r) * NS + q * 8];
        *(uint4*)(Bf + r * RS2 + q * 16) = *(const uint4*)&g_poutF[(size_t)(n0c + r) * NS + q * 8];
    }
    __syncthreads();

#pragma unroll
    for (int kstep = 0; kstep < 4; ++kstep) {
        int kb = kstep * 32;   // byte offset of 16-element k group
        uint32_t ah[2][4], al[2][4];
#pragma unroll
        for (int mt = 0; mt < 2; ++mt) {
            uint32_t off = (uint32_t)((wm * 32 + mt * 16 + lrow) * RS2 + kb + lhalf);
            ldsm_x4(ah[mt], smb + off);
            ldsm_x4(al[mt], smb + 18432 + off);
        }
#pragma unroll
        for (int nt = 0; nt < 8; ++nt) {
            int n0 = wn * 64 + nt * 8 + lr;
            int co = kb + lc * 4;
            uint32_t bf[2];
            bf[0] = *(const uint32_t*)(Bf + n0 * RS2 + co);
            bf[1] = *(const uint32_t*)(Bf + n0 * RS2 + co + 16);
#pragma unroll
            for (int mt = 0; mt < 2; ++mt) {
                mma16816h(acc[mt][nt], ah[mt], bf);
                mma16816h(acc[mt][nt], al[mt], bf);
            }
        }
    }
#pragma unroll
    for (int mt = 0; mt < 2; ++mt) {
        size_t mrow = (size_t)m0 + wm * 32 + mt * 16 + lr;
#pragma unroll
        for (int nt = 0; nt < 8; ++nt) {
            int n = n0c + wn * 64 + nt * 8 + lc * 2;
            *(float2*)&C[mrow * Hdim + n]       = make_float2(acc[mt][nt][0], acc[mt][nt][1]);
            *(float2*)&C[(mrow + 8) * Hdim + n] = make_float2(acc[mt][nt][2], acc[mt][nt][3]);
        }
    }
}

// ---------------- launch ----------------
extern "C" void kernel_launch(void* const* d_in, const int* in_sizes, int n_in,
                              void* d_out, int out_size) {
    const float* input = (const float*)d_in[0];
    const float* init  = (const float*)d_in[1];
    const float* pin   = (const float*)d_in[2];
    const float* pout  = (const float*)d_in[3];
    const float* freq  = (const float*)d_in[4];
    const float* dec   = (const float*)d_in[5];
    float* out = (float*)d_out;

    cudaFuncSetAttribute(gemmB_mma, cudaFuncAttributeMaxDynamicSharedMemorySize, GB_SMEM);

    long long tail = (long long)out_size - (long long)M_TOT * Hdim;
    int mode = 0;
    if (tail >= (long long)Bsz * NS * 2)  mode = 2;
    else if (tail >= (long long)Bsz * NS) mode = 1;

    taps_kernel<<<NTAP, NS>>>(freq, dec);
    prep_planes<<<512, 256>>>(pin, pout);
    gemmA_mma<<<M_TOT / 128, 256>>>(input);
    fir_kernel<<<Bsz * (Lseq / TL), 256>>>(init, out, mode);
    gemmB_mma<<<dim3(Hdim / 128, M_TOT / 128), 256, GB_SMEM>>>(out);
}